// round 1
// baseline (speedup 1.0000x reference)
#include <cuda_runtime.h>

#define Bz 8
#define L0c 384
#define Lr 385
#define LP 448
#define Dm 128
#define NH 8
#define NIT 4

// ---------------- scratch (device globals; no allocation allowed) ----------------
__device__ float g_unary[Bz*LP*Dm];
__device__ float g_qz[Bz*LP*Dm];
__device__ float g_P[Bz*LP*Dm];
__device__ float g_m1[Bz*LP];
__device__ float g_Tu[2*Dm*NH*Dm];        // [k][a][c][b]
__device__ float g_Tv[2*Dm*NH*Dm];        // [k][b][c][a]
__device__ float g_U[Bz*2*LP*NH*Dm];      // [z][k][i][c][b]
__device__ float g_V[Bz*2*LP*NH*Dm];      // [z][k][j][c][a]
__device__ float g_Hmat[(size_t)Bz*NH*LP*LP];   // F then H
__device__ float g_Gp[Bz*NH*LP*Dm];       // per-head partial G
__device__ float g_Hp[Bz*NH*LP*Dm];       // per-head partial Hm

// ---------------- prep ----------------
__global__ void prep_unary_kernel(const float* __restrict__ x,
                                  const float* __restrict__ mask) {
    int idx = blockIdx.x * blockDim.x + threadIdx.x;
    if (idx >= Bz*LP*Dm) return;
    int d = idx & 127;
    int zi = idx >> 7;
    int i = zi % LP, z = zi / LP;
    float v = 0.f;
    if (i >= 1 && i < Lr) v = x[(z*L0c + (i-1))*Dm + d];
    float m = (i == 0) ? 1.f : ((i < Lr) ? mask[z*L0c + (i-1)] : 0.f);
    g_unary[idx] = v;
    g_qz[idx]    = v * m;   // q_z = unary * m1
    g_P[idx]     = 0.f;     // padded rows must stay zero
    if (d == 0) g_m1[zi] = m;
}

__global__ void prep_T_kernel(const float* __restrict__ tern) {
    int idx = blockIdx.x * blockDim.x + threadIdx.x;
    if (idx >= 2*Dm*Dm*NH) return;
    int c = idx & 7;
    int r = idx >> 3;
    int b = r & 127; r >>= 7;
    int a = r & 127;
    int k = r >> 7;
    float v = tern[idx];                       // layout ((k*128+a)*128+b)*8+c
    g_Tu[((k*Dm + a)*NH + c)*Dm + b] = v;
    g_Tv[((k*Dm + b)*NH + c)*Dm + a] = v;
}

// ---------------- softmax over d for q_z -> P ----------------
__global__ void softmax_p_kernel() {
    int row = blockIdx.x;
    int z = row / Lr, i = row - z*Lr;
    const float* src = g_qz + (z*LP + i)*Dm;
    int t = threadIdx.x;
    float v = src[t];
    __shared__ float shm[4], shs[4];
    float m = v;
#pragma unroll
    for (int o = 16; o; o >>= 1) m = fmaxf(m, __shfl_xor_sync(0xffffffffu, m, o));
    if ((t & 31) == 0) shm[t >> 5] = m;
    __syncthreads();
    m = fmaxf(fmaxf(shm[0], shm[1]), fmaxf(shm[2], shm[3]));
    float e = __expf(v - m);
    float s = e;
#pragma unroll
    for (int o = 16; o; o >>= 1) s += __shfl_xor_sync(0xffffffffu, s, o);
    if ((t & 31) == 0) shs[t >> 5] = s;
    __syncthreads();
    s = (shs[0] + shs[1]) + (shs[2] + shs[3]);
    g_P[(z*LP + i)*Dm + t] = e / s * g_m1[z*LP + i];
}

// ---------------- U/V GEMM: C[448x1024] = P[z](448x128) @ T*(128x1024) ----------------
__global__ __launch_bounds__(256) void gemm_uv_kernel() {
    int inst = blockIdx.z;
    int uv = inst & 1, kg = (inst >> 1) & 1, z = inst >> 2;
    const float* A  = g_P + (z*LP)*Dm;
    const float* Bm = (uv ? g_Tv : g_Tu) + kg * (Dm*NH*Dm);
    float*       C  = (uv ? g_V : g_U) + (z*2 + kg) * (LP*NH*Dm);
    int m0 = blockIdx.y * 64, n0 = blockIdx.x * 64;
    __shared__ float As[16][68];
    __shared__ float Bs[16][64];
    int t = threadIdx.x, ty = t >> 4, tx = t & 15;
    int arow = t >> 2, acol = (t & 3) << 2;
    int brow = t >> 4, bcol = (t & 15) << 2;
    float acc[4][4] = {};
    for (int kt = 0; kt < Dm; kt += 16) {
        float4 av = *(const float4*)&A[(m0 + arow)*Dm + kt + acol];
        As[acol+0][arow] = av.x; As[acol+1][arow] = av.y;
        As[acol+2][arow] = av.z; As[acol+3][arow] = av.w;
        *(float4*)&Bs[brow][bcol] = *(const float4*)&Bm[(kt + brow)*1024 + n0 + bcol];
        __syncthreads();
#pragma unroll
        for (int kk = 0; kk < 16; kk++) {
            float a[4], b[4];
            *(float4*)a = *(const float4*)&As[kk][ty << 2];
            *(float4*)b = *(const float4*)&Bs[kk][tx << 2];
#pragma unroll
            for (int u = 0; u < 4; u++)
#pragma unroll
                for (int v = 0; v < 4; v++) acc[u][v] += a[u] * b[v];
        }
        __syncthreads();
    }
#pragma unroll
    for (int u = 0; u < 4; u++)
#pragma unroll
        for (int v = 0; v < 4; v++)
            C[(m0 + (ty<<2) + u)*1024 + n0 + (tx<<2) + v] = acc[u][v];
}

// ---------------- F GEMM (NT): F[i][j] = sum_b U[z,g(i,j),i,c,b] * P[z,j,b] ----------------
__global__ __launch_bounds__(256) void gemm_f_kernel() {
    int zc = blockIdx.z;
    int z = zc >> 3, c = zc & 7;
    int i0 = blockIdx.y * 64, j0 = blockIdx.x * 64;
    bool diag = (i0 == j0);
    int gsingle = (j0 > i0) ? 0 : 1;
    __shared__ float As[16][68];
    __shared__ float Bs[16][68];
    int t = threadIdx.x, ty = t >> 4, tx = t & 15;
    int lrow = t >> 2, lcol = (t & 3) << 2;
    float acc0[4][4] = {};
    float acc1[4][4] = {};
    const float* Bp = g_P + (z*LP)*Dm;
    int npass = diag ? 2 : 1;
    for (int p = 0; p < npass; p++) {
        int g = diag ? p : gsingle;
        const float* Au = g_U + ((z*2 + g)*LP)*1024 + c*Dm;
        for (int kt = 0; kt < Dm; kt += 16) {
            float4 av = *(const float4*)&Au[(i0 + lrow)*1024 + kt + lcol];
            As[lcol+0][lrow] = av.x; As[lcol+1][lrow] = av.y;
            As[lcol+2][lrow] = av.z; As[lcol+3][lrow] = av.w;
            float4 bv = *(const float4*)&Bp[(j0 + lrow)*Dm + kt + lcol];
            Bs[lcol+0][lrow] = bv.x; Bs[lcol+1][lrow] = bv.y;
            Bs[lcol+2][lrow] = bv.z; Bs[lcol+3][lrow] = bv.w;
            __syncthreads();
            if (p == 0) {
#pragma unroll
                for (int kk = 0; kk < 16; kk++) {
                    float a[4], b[4];
                    *(float4*)a = *(const float4*)&As[kk][ty << 2];
                    *(float4*)b = *(const float4*)&Bs[kk][tx << 2];
#pragma unroll
                    for (int u = 0; u < 4; u++)
#pragma unroll
                        for (int v = 0; v < 4; v++) acc0[u][v] += a[u] * b[v];
                }
            } else {
#pragma unroll
                for (int kk = 0; kk < 16; kk++) {
                    float a[4], b[4];
                    *(float4*)a = *(const float4*)&As[kk][ty << 2];
                    *(float4*)b = *(const float4*)&Bs[kk][tx << 2];
#pragma unroll
                    for (int u = 0; u < 4; u++)
#pragma unroll
                        for (int v = 0; v < 4; v++) acc1[u][v] += a[u] * b[v];
                }
            }
            __syncthreads();
        }
    }
    float* C = g_Hmat + (size_t)zc * (LP*LP);
#pragma unroll
    for (int u = 0; u < 4; u++) {
        int i = i0 + (ty << 2) + u;
#pragma unroll
        for (int v = 0; v < 4; v++) {
            int j = j0 + (tx << 2) + v;
            float val = acc0[u][v];
            if (diag) val = (i < j) ? acc0[u][v] : ((i > j) ? acc1[u][v] : 0.f);
            C[i*LP + j] = val;
        }
    }
}

// ---------------- H softmax over j ----------------
__global__ void hsoftmax_kernel() {
    int bid = blockIdx.x;
    int i = bid % Lr;
    int zc = bid / Lr;
    int z = zc >> 3;
    float* row = g_Hmat + (size_t)zc * (LP*LP) + (size_t)i * LP;
    int t = threadIdx.x;
    if (i == 0) {
        for (int j = t; j < Lr; j += 128) row[j] = 0.f;
        return;
    }
    float mi = g_m1[z*LP + i];
    float lv[4];
    float mx = -3.4e38f;
#pragma unroll
    for (int r = 0; r < 4; r++) {
        int j = t + r*128;
        float l = -3.4e38f;
        if (j < Lr) {
            bool ok = (mi != 0.f) && (g_m1[z*LP + j] != 0.f) && (j != i);
            l = ok ? row[j] * 128.f : -1e9f;
        }
        lv[r] = l;
        mx = fmaxf(mx, l);
    }
    __shared__ float shm[4], shs[4];
#pragma unroll
    for (int o = 16; o; o >>= 1) mx = fmaxf(mx, __shfl_xor_sync(0xffffffffu, mx, o));
    if ((t & 31) == 0) shm[t >> 5] = mx;
    __syncthreads();
    mx = fmaxf(fmaxf(shm[0], shm[1]), fmaxf(shm[2], shm[3]));
    float ev[4];
    float s = 0.f;
#pragma unroll
    for (int r = 0; r < 4; r++) {
        int j = t + r*128;
        ev[r] = 0.f;
        if (j < Lr) { ev[r] = __expf(lv[r] - mx); s += ev[r]; }
    }
#pragma unroll
    for (int o = 16; o; o >>= 1) s += __shfl_xor_sync(0xffffffffu, s, o);
    if ((t & 31) == 0) shs[t >> 5] = s;
    __syncthreads();
    s = (shs[0] + shs[1]) + (shs[2] + shs[3]);
    float inv = 1.f / s;
#pragma unroll
    for (int r = 0; r < 4; r++) {
        int j = t + r*128;
        if (j < Lr) row[j] = ev[r] * inv;
    }
}

// ---------------- G GEMM (NN): G[i][a] += sum_j Hsel[i][j] * V[z,g,j,c,a] ----------------
__global__ __launch_bounds__(256) void gemm_g_kernel() {
    int c = blockIdx.x, i0 = blockIdx.y * 64, z = blockIdx.z;
    const float* Hmp = g_Hmat + (size_t)(z*NH + c) * (LP*LP);
    __shared__ float Hs[16][68];
    __shared__ float Vs[16][128];
    int t = threadIdx.x, ty = t >> 4, tx = t & 15;
    int hrow = t >> 2, hcol = (t & 3) << 2;
    int vrow = t >> 4, vcol = (t & 15) << 3;
    float acc[4][8] = {};
    for (int j0 = 0; j0 < LP; j0 += 16) {
        int mode = (j0 >= i0 + 64) ? 0 : ((j0 + 16 <= i0) ? 1 : 2);
        int npass = (mode == 2) ? 2 : 1;
        float4 hv = *(const float4*)&Hmp[(i0 + hrow)*LP + j0 + hcol];
        float hraw[4] = {hv.x, hv.y, hv.z, hv.w};
        for (int p = 0; p < npass; p++) {
            int g = (mode == 2) ? p : mode;
#pragma unroll
            for (int u = 0; u < 4; u++) {
                float val = hraw[u];
                if (mode == 2) {
                    int ig = i0 + hrow, jg = j0 + hcol + u;
                    bool keep = (g == 0) ? (jg > ig) : (jg < ig);
                    if (!keep) val = 0.f;
                }
                Hs[hcol + u][hrow] = val;
            }
            const float* Vp = &g_V[((z*2 + g)*LP + j0 + vrow)*1024 + c*Dm + vcol];
            *(float4*)&Vs[vrow][vcol]     = *(const float4*)&Vp[0];
            *(float4*)&Vs[vrow][vcol + 4] = *(const float4*)&Vp[4];
            __syncthreads();
#pragma unroll
            for (int kk = 0; kk < 16; kk++) {
                float a[4], b[8];
                *(float4*)a       = *(const float4*)&Hs[kk][ty << 2];
                *(float4*)b       = *(const float4*)&Vs[kk][tx << 3];
                *(float4*)(b + 4) = *(const float4*)&Vs[kk][(tx << 3) + 4];
#pragma unroll
                for (int u = 0; u < 4; u++)
#pragma unroll
                    for (int v = 0; v < 8; v++) acc[u][v] += a[u] * b[v];
            }
            __syncthreads();
        }
    }
    float* out = &g_Gp[((z*NH + c)*LP + i0)*Dm];
#pragma unroll
    for (int u = 0; u < 4; u++)
#pragma unroll
        for (int v = 0; v < 8; v++)
            out[((ty<<2) + u)*Dm + (tx<<3) + v] = acc[u][v];
}

// ---------------- Hm GEMM (TN): Hm[j][b] += sum_i Hsel[i][j] * U[z,g,i,c,b] ----------------
__global__ __launch_bounds__(256) void gemm_hm_kernel() {
    int c = blockIdx.x, j0 = blockIdx.y * 64, z = blockIdx.z;
    const float* Hmp = g_Hmat + (size_t)(z*NH + c) * (LP*LP);
    __shared__ float Hs[16][64];
    __shared__ float Us[16][128];
    int t = threadIdx.x, ty = t >> 4, tx = t & 15;
    int hrow = t >> 4, hcol = (t & 15) << 2;
    int urow = t >> 4, ucol = (t & 15) << 3;
    float acc[4][8] = {};
    for (int i0 = 0; i0 < LP; i0 += 16) {
        int mode = (i0 + 16 <= j0) ? 0 : ((i0 >= j0 + 64) ? 1 : 2);
        int npass = (mode == 2) ? 2 : 1;
        float4 hv = *(const float4*)&Hmp[(i0 + hrow)*LP + j0 + hcol];
        float hraw[4] = {hv.x, hv.y, hv.z, hv.w};
        for (int p = 0; p < npass; p++) {
            int g = (mode == 2) ? p : mode;
#pragma unroll
            for (int u = 0; u < 4; u++) {
                float val = hraw[u];
                if (mode == 2) {
                    int ig = i0 + hrow, jg = j0 + hcol + u;
                    bool keep = (g == 0) ? (ig < jg) : (ig > jg);
                    if (!keep) val = 0.f;
                }
                Hs[hrow][hcol + u] = val;
            }
            const float* Up = &g_U[((z*2 + g)*LP + i0 + urow)*1024 + c*Dm + ucol];
            *(float4*)&Us[urow][ucol]     = *(const float4*)&Up[0];
            *(float4*)&Us[urow][ucol + 4] = *(const float4*)&Up[4];
            __syncthreads();
#pragma unroll
            for (int kk = 0; kk < 16; kk++) {
                float a[4], b[8];
                *(float4*)a       = *(const float4*)&Hs[kk][ty << 2];
                *(float4*)b       = *(const float4*)&Us[kk][tx << 3];
                *(float4*)(b + 4) = *(const float4*)&Us[kk][(tx << 3) + 4];
#pragma unroll
                for (int u = 0; u < 4; u++)
#pragma unroll
                    for (int v = 0; v < 8; v++) acc[u][v] += a[u] * b[v];
            }
            __syncthreads();
        }
    }
    float* out = &g_Hp[((z*NH + c)*LP + j0)*Dm];
#pragma unroll
    for (int u = 0; u < 4; u++)
#pragma unroll
        for (int v = 0; v < 8; v++)
            out[((ty<<2) + u)*Dm + (tx<<3) + v] = acc[u][v];
}

// ---------------- q_z = (unary + sum_c Gp + sum_c Hp) * m1 ----------------
__global__ void reduce_qz_kernel() {
    int idx = blockIdx.x * blockDim.x + threadIdx.x;
    if (idx >= Bz*LP*Dm) return;
    int d = idx & 127;
    int zi = idx >> 7;
    int i = zi % LP, z = zi / LP;
    float s = g_unary[idx];
#pragma unroll
    for (int c = 0; c < NH; c++) {
        int o = ((z*NH + c)*LP + i)*Dm + d;
        s += g_Gp[o] + g_Hp[o];
    }
    g_qz[idx] = s * g_m1[zi];
}

// ---------------- strip root and emit ----------------
__global__ void out_kernel(float* __restrict__ out) {
    int idx = blockIdx.x * blockDim.x + threadIdx.x;
    if (idx >= Bz*L0c*Dm) return;
    int d = idx & 127;
    int zt = idx >> 7;
    int tt = zt % L0c, z = zt / L0c;
    out[idx] = g_qz[(z*LP + 1 + tt)*Dm + d];
}

extern "C" void kernel_launch(void* const* d_in, const int* in_sizes, int n_in,
                              void* d_out, int out_size) {
    const float* x = nullptr;
    const float* mask = nullptr;
    const float* tern = nullptr;
    for (int i = 0; i < n_in; i++) {
        if (in_sizes[i] == Bz*L0c*Dm)      x    = (const float*)d_in[i];
        else if (in_sizes[i] == Bz*L0c)    mask = (const float*)d_in[i];
        else if (in_sizes[i] == 2*Dm*Dm*NH) tern = (const float*)d_in[i];
    }
    if (!x || !mask || !tern) return;

    prep_unary_kernel<<<(Bz*LP*Dm + 255)/256, 256>>>(x, mask);
    prep_T_kernel<<<(2*Dm*Dm*NH + 255)/256, 256>>>(tern);

    for (int it = 0; it < NIT; it++) {
        softmax_p_kernel<<<Bz*Lr, 128>>>();
        gemm_uv_kernel<<<dim3(16, 7, 32), 256>>>();
        gemm_f_kernel<<<dim3(7, 7, Bz*NH), 256>>>();
        hsoftmax_kernel<<<Bz*NH*Lr, 128>>>();
        gemm_g_kernel<<<dim3(NH, 7, Bz), 256>>>();
        gemm_hm_kernel<<<dim3(NH, 7, Bz), 256>>>();
        reduce_qz_kernel<<<(Bz*LP*Dm + 255)/256, 256>>>();
    }
    out_kernel<<<(Bz*L0c*Dm + 255)/256, 256>>>((float*)d_out);
}

// round 2
// speedup vs baseline: 1.3536x; 1.3536x over previous
#include <cuda_runtime.h>

#define Bz 8
#define L0c 384
#define Lr 385
#define LP 448
#define Dm 128
#define NH 8
#define NIT 4
#define MST (LP*NH)   // stacked rows for F: 3584

// ---------------- scratch ----------------
__device__ float g_unary[Bz*LP*Dm];
__device__ float g_qz[Bz*LP*Dm];
__device__ float g_P[Bz*LP*Dm];
__device__ float g_m1[Bz*LP];
__device__ float g_Tu[2*Dm*NH*Dm];        // [k][a][c][b]
__device__ float g_Tv[2*Dm*NH*Dm];        // [k][b][c][a]
__device__ float g_U[Bz*2*LP*NH*Dm];      // [z][g][i][(c,b)] == stacked [m=(i*8+c)][b]
__device__ float g_V[Bz*2*LP*NH*Dm];      // [z][g][j][(c,a)]
__device__ float g_Hmat[(size_t)Bz*NH*LP*LP];
__device__ float g_Gp[Bz*NH*LP*Dm];
__device__ float g_Hp[Bz*NH*LP*Dm];

// ---------------- prep ----------------
__global__ void prep_unary_kernel(const float* __restrict__ x,
                                  const float* __restrict__ mask) {
    int idx = blockIdx.x * blockDim.x + threadIdx.x;
    if (idx >= Bz*LP*Dm) return;
    int d = idx & 127;
    int zi = idx >> 7;
    int i = zi % LP, z = zi / LP;
    float v = 0.f;
    if (i >= 1 && i < Lr) v = x[(z*L0c + (i-1))*Dm + d];
    float m = (i == 0) ? 1.f : ((i < Lr) ? mask[z*L0c + (i-1)] : 0.f);
    g_unary[idx] = v;
    g_qz[idx]    = v * m;
    g_P[idx]     = 0.f;
    if (d == 0) g_m1[zi] = m;
}

__global__ void prep_T_kernel(const float* __restrict__ tern) {
    int idx = blockIdx.x * blockDim.x + threadIdx.x;
    if (idx >= 2*Dm*Dm*NH) return;
    int c = idx & 7;
    int r = idx >> 3;
    int b = r & 127; r >>= 7;
    int a = r & 127;
    int k = r >> 7;
    float v = tern[idx];
    g_Tu[((k*Dm + a)*NH + c)*Dm + b] = v;
    g_Tv[((k*Dm + b)*NH + c)*Dm + a] = v;
}

// ---------------- softmax over d ----------------
__global__ void softmax_p_kernel() {
    int row = blockIdx.x;
    int z = row / Lr, i = row - z*Lr;
    const float* src = g_qz + (z*LP + i)*Dm;
    int t = threadIdx.x;
    float v = src[t];
    __shared__ float shm[4], shs[4];
    float m = v;
#pragma unroll
    for (int o = 16; o; o >>= 1) m = fmaxf(m, __shfl_xor_sync(0xffffffffu, m, o));
    if ((t & 31) == 0) shm[t >> 5] = m;
    __syncthreads();
    m = fmaxf(fmaxf(shm[0], shm[1]), fmaxf(shm[2], shm[3]));
    float e = __expf(v - m);
    float s = e;
#pragma unroll
    for (int o = 16; o; o >>= 1) s += __shfl_xor_sync(0xffffffffu, s, o);
    if ((t & 31) == 0) shs[t >> 5] = s;
    __syncthreads();
    s = (shs[0] + shs[1]) + (shs[2] + shs[3]);
    g_P[(z*LP + i)*Dm + t] = e / s * g_m1[z*LP + i];
}

// ---------------- UV: C[448x1024] = P(448x128) @ T(128x1024), tile 64x128 ----------------
__global__ __launch_bounds__(256) void gemm_uv_kernel() {
    int inst = blockIdx.z;
    int uv = inst & 1, kg = (inst >> 1) & 1, z = inst >> 2;
    const float* A  = g_P + (size_t)(z*LP)*Dm;
    const float* Bm = (uv ? g_Tv : g_Tu) + kg * (Dm*NH*Dm);
    float*       C  = (uv ? g_V : g_U) + (size_t)(z*2 + kg) * (LP*NH*Dm);
    int m0 = blockIdx.y * 64, n0 = blockIdx.x * 128;
    __shared__ float As[16][68];
    __shared__ float Bs[16][128];
    int t = threadIdx.x, ty = t >> 4, tx = t & 15;
    int arow = t >> 2, acol = (t & 3) << 2;
    int brow = t >> 4, bcol = (t & 15) << 3;
    float4 pa, pb0, pb1;
    pa  = *(const float4*)&A[(m0 + arow)*Dm + acol];
    pb0 = *(const float4*)&Bm[brow*1024 + n0 + bcol];
    pb1 = *(const float4*)&Bm[brow*1024 + n0 + bcol + 4];
    float acc[4][8] = {};
    for (int s = 0; s < 8; s++) {
        As[acol+0][arow]=pa.x; As[acol+1][arow]=pa.y; As[acol+2][arow]=pa.z; As[acol+3][arow]=pa.w;
        *(float4*)&Bs[brow][bcol]   = pb0;
        *(float4*)&Bs[brow][bcol+4] = pb1;
        __syncthreads();
        if (s < 7) {
            int kt = (s+1) << 4;
            pa  = *(const float4*)&A[(m0 + arow)*Dm + kt + acol];
            pb0 = *(const float4*)&Bm[(kt+brow)*1024 + n0 + bcol];
            pb1 = *(const float4*)&Bm[(kt+brow)*1024 + n0 + bcol + 4];
        }
#pragma unroll
        for (int kk = 0; kk < 16; kk++) {
            float a[4], b[8];
            *(float4*)a     = *(const float4*)&As[kk][ty << 2];
            *(float4*)b     = *(const float4*)&Bs[kk][tx << 2];
            *(float4*)(b+4) = *(const float4*)&Bs[kk][64 + (tx << 2)];
#pragma unroll
            for (int u = 0; u < 4; u++)
#pragma unroll
                for (int v = 0; v < 8; v++) acc[u][v] = fmaf(a[u], b[v], acc[u][v]);
        }
        __syncthreads();
    }
#pragma unroll
    for (int u = 0; u < 4; u++) {
        size_t ro = (size_t)(m0 + (ty<<2) + u)*1024 + n0;
        *(float4*)&C[ro + (tx<<2)]      = *(float4*)&acc[u][0];
        *(float4*)&C[ro + 64 + (tx<<2)] = *(float4*)&acc[u][4];
    }
}

// ---------------- F: C[(i,c)=3584 x j=448] = U[m][b] . P[j][b]  (NT), tile 128x64 ----------------
__global__ __launch_bounds__(256) void gemm_f_kernel() {
    int z = blockIdx.z;
    int m0 = blockIdx.y * 128, j0 = blockIdx.x * 64;
    int ilo = m0 >> 3;
    int mode = (ilo + 16 <= j0) ? 0 : ((ilo >= j0 + 64) ? 1 : 2);
    __shared__ float As[16][132];
    __shared__ float Bs[16][68];
    int t = threadIdx.x, ty = t >> 4, tx = t & 15;
    int arow = t >> 1, acolh = (t & 1) << 3;
    int brow = t >> 2, bcol = (t & 3) << 2;
    const float* Bp = g_P + (size_t)(z*LP)*Dm;
    int npass = (mode == 2) ? 2 : 1;
    for (int p = 0; p < npass; p++) {
        int g = (mode == 2) ? p : mode;
        const float* Au = g_U + (size_t)(z*2+g)*(LP*NH*Dm);
        float acc[8][4] = {};
        float4 pa0 = *(const float4*)&Au[(size_t)(m0+arow)*Dm + acolh];
        float4 pa1 = *(const float4*)&Au[(size_t)(m0+arow)*Dm + acolh + 4];
        float4 pb  = *(const float4*)&Bp[(j0+brow)*Dm + bcol];
        for (int s = 0; s < 8; s++) {
            As[acolh+0][arow]=pa0.x; As[acolh+1][arow]=pa0.y; As[acolh+2][arow]=pa0.z; As[acolh+3][arow]=pa0.w;
            As[acolh+4][arow]=pa1.x; As[acolh+5][arow]=pa1.y; As[acolh+6][arow]=pa1.z; As[acolh+7][arow]=pa1.w;
            Bs[bcol+0][brow]=pb.x; Bs[bcol+1][brow]=pb.y; Bs[bcol+2][brow]=pb.z; Bs[bcol+3][brow]=pb.w;
            __syncthreads();
            if (s < 7) {
                int kt = (s+1) << 4;
                pa0 = *(const float4*)&Au[(size_t)(m0+arow)*Dm + kt + acolh];
                pa1 = *(const float4*)&Au[(size_t)(m0+arow)*Dm + kt + acolh + 4];
                pb  = *(const float4*)&Bp[(j0+brow)*Dm + kt + bcol];
            }
#pragma unroll
            for (int kk = 0; kk < 16; kk++) {
                float a[8], b[4];
                *(float4*)a     = *(const float4*)&As[kk][ty << 3];
                *(float4*)(a+4) = *(const float4*)&As[kk][(ty << 3) + 4];
                *(float4*)b     = *(const float4*)&Bs[kk][tx << 2];
#pragma unroll
                for (int u = 0; u < 8; u++)
#pragma unroll
                    for (int v = 0; v < 4; v++) acc[u][v] = fmaf(a[u], b[v], acc[u][v]);
            }
            __syncthreads();
        }
        // epilogue
#pragma unroll
        for (int u = 0; u < 8; u++) {
            int m = m0 + (ty << 3) + u;
            int i = m >> 3, cc = m & 7;
            size_t off = ((size_t)(z*NH + cc)*LP + i)*LP + j0 + (tx << 2);
            if (mode != 2) {
                *(float4*)&g_Hmat[off] = *(float4*)&acc[u][0];
            } else if (p == 0) {
                float4 val;
                int jb = j0 + (tx << 2);
                val.x = (jb+0 > i) ? acc[u][0] : 0.f;
                val.y = (jb+1 > i) ? acc[u][1] : 0.f;
                val.z = (jb+2 > i) ? acc[u][2] : 0.f;
                val.w = (jb+3 > i) ? acc[u][3] : 0.f;
                *(float4*)&g_Hmat[off] = val;
            } else {
                int jb = j0 + (tx << 2);
#pragma unroll
                for (int v = 0; v < 4; v++)
                    if (jb + v < i) g_Hmat[off + v] = acc[u][v];
            }
        }
    }
}

// ---------------- H softmax over j ----------------
__global__ void hsoftmax_kernel() {
    int bid = blockIdx.x;
    int i = bid % Lr;
    int zc = bid / Lr;
    int z = zc >> 3;
    float* row = g_Hmat + (size_t)zc * (LP*LP) + (size_t)i * LP;
    int t = threadIdx.x;
    if (i == 0) {
        for (int j = t; j < Lr; j += 128) row[j] = 0.f;
        return;
    }
    float mi = g_m1[z*LP + i];
    float lv[4];
    float mx = -3.4e38f;
#pragma unroll
    for (int r = 0; r < 4; r++) {
        int j = t + r*128;
        float l = -3.4e38f;
        if (j < Lr) {
            bool ok = (mi != 0.f) && (g_m1[z*LP + j] != 0.f) && (j != i);
            l = ok ? row[j] * 128.f : -1e9f;
        }
        lv[r] = l;
        mx = fmaxf(mx, l);
    }
    __shared__ float shm[4], shs[4];
#pragma unroll
    for (int o = 16; o; o >>= 1) mx = fmaxf(mx, __shfl_xor_sync(0xffffffffu, mx, o));
    if ((t & 31) == 0) shm[t >> 5] = mx;
    __syncthreads();
    mx = fmaxf(fmaxf(shm[0], shm[1]), fmaxf(shm[2], shm[3]));
    float ev[4];
    float s = 0.f;
#pragma unroll
    for (int r = 0; r < 4; r++) {
        int j = t + r*128;
        ev[r] = 0.f;
        if (j < Lr) { ev[r] = __expf(lv[r] - mx); s += ev[r]; }
    }
#pragma unroll
    for (int o = 16; o; o >>= 1) s += __shfl_xor_sync(0xffffffffu, s, o);
    if ((t & 31) == 0) shs[t >> 5] = s;
    __syncthreads();
    s = (shs[0] + shs[1]) + (shs[2] + shs[3]);
    float inv = 1.f / s;
#pragma unroll
    for (int r = 0; r < 4; r++) {
        int j = t + r*128;
        if (j < Lr) row[j] = ev[r] * inv;
    }
}

// ---------------- G: C[i 64 x a 128] = Hsel[i][j] @ V[j][(c,a)] (NN over j) ----------------
__global__ __launch_bounds__(256) void gemm_g_kernel() {
    int c = blockIdx.x, i0 = blockIdx.y * 64, z = blockIdx.z;
    const float* Hmp = g_Hmat + (size_t)(z*NH + c) * (LP*LP);
    __shared__ float As[16][68];
    __shared__ float Bs[16][128];
    int t = threadIdx.x, ty = t >> 4, tx = t & 15;
    int arow = t >> 2, acol = (t & 3) << 2;
    int brow = t >> 4, bcol = (t & 15) << 3;
    float acc[4][8] = {};
    for (int ss = 0; ss < 28; ss++) {
        int j0s = ss << 4;
        int mode = (j0s >= i0 + 64) ? 0 : ((j0s + 16 <= i0) ? 1 : 2);
        int npass = (mode == 2) ? 2 : 1;
        float4 hv = *(const float4*)&Hmp[(size_t)(i0+arow)*LP + j0s + acol];
        float h4[4] = {hv.x, hv.y, hv.z, hv.w};
        for (int p = 0; p < npass; p++) {
            int g = (mode == 2) ? p : mode;
#pragma unroll
            for (int u = 0; u < 4; u++) {
                float val = h4[u];
                if (mode == 2) {
                    int jg = j0s + acol + u, ig = i0 + arow;
                    bool keep = (g == 0) ? (jg > ig) : (jg < ig);
                    if (!keep) val = 0.f;
                }
                As[acol+u][arow] = val;
            }
            const float* Vp = g_V + (size_t)(z*2+g)*(LP*NH*Dm)
                             + (size_t)(j0s + brow)*1024 + c*Dm + bcol;
            *(float4*)&Bs[brow][bcol]   = *(const float4*)&Vp[0];
            *(float4*)&Bs[brow][bcol+4] = *(const float4*)&Vp[4];
            __syncthreads();
#pragma unroll
            for (int kk = 0; kk < 16; kk++) {
                float a[4], b[8];
                *(float4*)a     = *(const float4*)&As[kk][ty << 2];
                *(float4*)b     = *(const float4*)&Bs[kk][tx << 2];
                *(float4*)(b+4) = *(const float4*)&Bs[kk][64 + (tx << 2)];
#pragma unroll
                for (int u = 0; u < 4; u++)
#pragma unroll
                    for (int v = 0; v < 8; v++) acc[u][v] = fmaf(a[u], b[v], acc[u][v]);
            }
            __syncthreads();
        }
    }
    float* out = &g_Gp[((size_t)(z*NH + c)*LP + i0)*Dm];
#pragma unroll
    for (int u = 0; u < 4; u++) {
        size_t ro = (size_t)((ty<<2) + u)*Dm;
        *(float4*)&out[ro + (tx<<2)]      = *(float4*)&acc[u][0];
        *(float4*)&out[ro + 64 + (tx<<2)] = *(float4*)&acc[u][4];
    }
}

// ---------------- Hm: C[j 64 x b 128] = Hsel^T[j][i] @ U[i][(c,b)] (TN over i) ----------------
__global__ __launch_bounds__(256) void gemm_hm_kernel() {
    int c = blockIdx.x, j0 = blockIdx.y * 64, z = blockIdx.z;
    const float* Hmp = g_Hmat + (size_t)(z*NH + c) * (LP*LP);
    __shared__ float As[16][68];
    __shared__ float Bs[16][128];
    int t = threadIdx.x, ty = t >> 4, tx = t & 15;
    int irow = t >> 4, jcol = (t & 15) << 2;
    int brow = t >> 4, bcol = (t & 15) << 3;
    float acc[4][8] = {};
    for (int ss = 0; ss < 28; ss++) {
        int i0s = ss << 4;
        int mode = (i0s + 16 <= j0) ? 0 : ((i0s >= j0 + 64) ? 1 : 2);
        int npass = (mode == 2) ? 2 : 1;
        float4 hv = *(const float4*)&Hmp[(size_t)(i0s+irow)*LP + j0 + jcol];
        float h4[4] = {hv.x, hv.y, hv.z, hv.w};
        for (int p = 0; p < npass; p++) {
            int g = (mode == 2) ? p : mode;
#pragma unroll
            for (int u = 0; u < 4; u++) {
                float val = h4[u];
                if (mode == 2) {
                    int ig = i0s + irow, jg = j0 + jcol + u;
                    bool keep = (g == 0) ? (ig < jg) : (ig > jg);
                    if (!keep) val = 0.f;
                }
                As[irow][jcol+u] = val;
            }
            const float* Up = g_U + (size_t)(z*2+g)*(LP*NH*Dm)
                             + (size_t)(i0s + brow)*1024 + c*Dm + bcol;
            *(float4*)&Bs[brow][bcol]   = *(const float4*)&Up[0];
            *(float4*)&Bs[brow][bcol+4] = *(const float4*)&Up[4];
            __syncthreads();
#pragma unroll
            for (int kk = 0; kk < 16; kk++) {
                float a[4], b[8];
                *(float4*)a     = *(const float4*)&As[kk][ty << 2];
                *(float4*)b     = *(const float4*)&Bs[kk][tx << 2];
                *(float4*)(b+4) = *(const float4*)&Bs[kk][64 + (tx << 2)];
#pragma unroll
                for (int u = 0; u < 4; u++)
#pragma unroll
                    for (int v = 0; v < 8; v++) acc[u][v] = fmaf(a[u], b[v], acc[u][v]);
            }
            __syncthreads();
        }
    }
    float* out = &g_Hp[((size_t)(z*NH + c)*LP + j0)*Dm];
#pragma unroll
    for (int u = 0; u < 4; u++) {
        size_t ro = (size_t)((ty<<2) + u)*Dm;
        *(float4*)&out[ro + (tx<<2)]      = *(float4*)&acc[u][0];
        *(float4*)&out[ro + 64 + (tx<<2)] = *(float4*)&acc[u][4];
    }
}

// ---------------- q_z = (unary + sum_c Gp + sum_c Hp) * m1 ----------------
__global__ void reduce_qz_kernel() {
    int idx = blockIdx.x * blockDim.x + threadIdx.x;
    if (idx >= Bz*LP*Dm) return;
    int d = idx & 127;
    int zi = idx >> 7;
    int i = zi % LP, z = zi / LP;
    float s = g_unary[idx];
#pragma unroll
    for (int c = 0; c < NH; c++) {
        size_t o = ((size_t)(z*NH + c)*LP + i)*Dm + d;
        s += g_Gp[o] + g_Hp[o];
    }
    g_qz[idx] = s * g_m1[zi];
}

__global__ void out_kernel(float* __restrict__ out) {
    int idx = blockIdx.x * blockDim.x + threadIdx.x;
    if (idx >= Bz*L0c*Dm) return;
    int d = idx & 127;
    int zt = idx >> 7;
    int tt = zt % L0c, z = zt / L0c;
    out[idx] = g_qz[(z*LP + 1 + tt)*Dm + d];
}

extern "C" void kernel_launch(void* const* d_in, const int* in_sizes, int n_in,
                              void* d_out, int out_size) {
    const float* x = nullptr;
    const float* mask = nullptr;
    const float* tern = nullptr;
    for (int i = 0; i < n_in; i++) {
        if (in_sizes[i] == Bz*L0c*Dm)       x    = (const float*)d_in[i];
        else if (in_sizes[i] == Bz*L0c)     mask = (const float*)d_in[i];
        else if (in_sizes[i] == 2*Dm*Dm*NH) tern = (const float*)d_in[i];
    }
    if (!x || !mask || !tern) return;

    prep_unary_kernel<<<(Bz*LP*Dm + 255)/256, 256>>>(x, mask);
    prep_T_kernel<<<(2*Dm*Dm*NH + 255)/256, 256>>>(tern);

    for (int it = 0; it < NIT; it++) {
        softmax_p_kernel<<<Bz*Lr, 128>>>();
        gemm_uv_kernel<<<dim3(8, 7, 32), 256>>>();
        gemm_f_kernel<<<dim3(7, 28, Bz), 256>>>();
        hsoftmax_kernel<<<Bz*NH*Lr, 128>>>();
        gemm_g_kernel<<<dim3(NH, 7, Bz), 256>>>();
        gemm_hm_kernel<<<dim3(NH, 7, Bz), 256>>>();
        reduce_qz_kernel<<<(Bz*LP*Dm + 255)/256, 256>>>();
    }
    out_kernel<<<(Bz*L0c*Dm + 255)/256, 256>>>((float*)d_out);
}